// round 11
// baseline (speedup 1.0000x reference)
#include <cuda_runtime.h>
#include <math.h>

#define NB 4
#define W 512
#define H 512
#define K 256
#define HW (W*H)
#define BORDER 32
#define CHUNK 4096
#define SBLK (NB*HW/CHUNK)   // 256 stats blocks
#define LBLK 256             // loss blocks (256 thr, 4 float4 groups each)

// Scratch (device globals; no allocation allowed)
__device__ float  g_stats[NB*(K+1)*8];   // cnt, sum_col, sum_row, sum_inj, sum_t0, sum_t1, sum_rot, sum_sca
__device__ int    g_bbox[NB*K*4];        // src bbox: minr, maxr, minc, maxc
__device__ float  g_coef[NB*K*6];        // affine Hinv
__device__ int    g_dbox[NB*K*4];        // dest bbox (inclusive); empty if r0>r1
__device__ float  g_proj[NB*HW];
__device__ double g_loss_sq, g_loss_ab;
__device__ unsigned g_cnt_stats;
__device__ unsigned g_cnt_loss;

// ---------------------------------------------------------------------------
__global__ void init_kernel() {
    int gid = blockIdx.x*blockDim.x + threadIdx.x;
    int stride = gridDim.x*blockDim.x;
    for (int i = gid; i < NB*(K+1)*8; i += stride) g_stats[i] = 0.f;
    for (int i = gid; i < NB*K*4; i += stride)
        g_bbox[i] = (i & 1) ? (int)0x80000000 : 0x7fffffff;
    if (gid == 0) {
        g_cnt_stats = 0u; g_cnt_loss = 0u;
        g_loss_sq = 0.0;  g_loss_ab = 0.0;
    }
}

// ---------------------------------------------------------------------------
// Segment sums + source bboxes. 4 pixels/thread (float4); warp-segmented scan
// over thread aggregates when each thread's 4 labels are uniform; per-pixel
// shared-atomic fallback otherwise. Last-done block runs prep.
__global__ void stats_prep_kernel(const int*   __restrict__ labels,
                                  const float* __restrict__ inj,
                                  const float* __restrict__ trs,
                                  const float* __restrict__ rot,
                                  const float* __restrict__ sca) {
    __shared__ float s_acc[(K+1)*8];
    __shared__ int   s_bb[(K+1)*4];
    __shared__ bool  s_last;
    const int tid  = threadIdx.x;
    const int lane = tid & 31;
    for (int i = tid; i < (K+1)*8; i += 256) s_acc[i] = 0.f;
    for (int i = tid; i < (K+1)*4; i += 256)
        s_bb[i] = (i & 1) ? (int)0x80000000 : 0x7fffffff;

    const int base = blockIdx.x * CHUNK;
    // zero this block's slice of g_proj (float4)
    {
        float4 z4 = make_float4(0.f,0.f,0.f,0.f);
        float4* pz = (float4*)(g_proj + base);
#pragma unroll
        for (int j = 0; j < CHUNK/1024; j++) pz[j*256 + tid] = z4;
    }
    __syncthreads();

    const unsigned FULL = 0xFFFFFFFFu;
    const int b = base >> 18;
    const float* t0p = trs + (size_t)b*2*HW;
    const float* t1p = t0p + HW;

#pragma unroll
    for (int j = 0; j < CHUNK/1024; j++) {
        int idx = base + j*1024 + tid*4;        // first pixel of this thread's group
        int rc  = idx & (HW-1);
        int4   l4 = *(const int4*)  (labels + idx);
        float4 a0 = *(const float4*)(inj + idx);
        float4 a1 = *(const float4*)(t0p + rc);
        float4 a2 = *(const float4*)(t1p + rc);
        float4 a3 = *(const float4*)(rot + idx);
        float4 a4 = *(const float4*)(sca + idx);

        bool uni = (l4.x == l4.y) & (l4.y == l4.z) & (l4.z == l4.w);
        if (__all_sync(FULL, uni)) {
            int lab = l4.x;
            float p0 = (a0.x + a0.y) + (a0.z + a0.w);
            float p1 = (a1.x + a1.y) + (a1.z + a1.w);
            float p2 = (a2.x + a2.y) + (a2.z + a2.w);
            float p3 = (a3.x + a3.y) + (a3.z + a3.w);
            float p4 = (a4.x + a4.y) + (a4.z + a4.w);

            int labp = __shfl_up_sync(FULL, lab, 1);
            bool head = (lane == 0) || (lab != labp);
            unsigned hm = __ballot_sync(FULL, head);
            unsigned le = FULL >> (31 - lane);
            int segstart = 31 - __clz(hm & le);
            bool tail = (lane == 31) || ((hm >> (lane+1)) & 1u);

#pragma unroll
            for (int d = 1; d < 32; d <<= 1) {
                float b0 = __shfl_up_sync(FULL, p0, d);
                float b1 = __shfl_up_sync(FULL, p1, d);
                float b2 = __shfl_up_sync(FULL, p2, d);
                float b3 = __shfl_up_sync(FULL, p3, d);
                float b4 = __shfl_up_sync(FULL, p4, d);
                if (lane >= d) { p0 += b0; p1 += b1; p2 += b2; p3 += b3; p4 += b4; }
            }
            int src = (segstart > 0) ? (segstart - 1) : 0;
            float q0 = __shfl_sync(FULL, p0, src);
            float q1 = __shfl_sync(FULL, p1, src);
            float q2 = __shfl_sync(FULL, p2, src);
            float q3 = __shfl_sync(FULL, p3, src);
            float q4 = __shfl_sync(FULL, p4, src);

            if (tail && lab >= 1 && lab <= K) {
                float z = (segstart > 0) ? 1.f : 0.f;
                float s0 = p0 - z*q0, s1 = p1 - z*q1, s2 = p2 - z*q2;
                float s3 = p3 - z*q3, s4 = p4 - z*q4;
                int n   = (lane - segstart + 1) * 4;
                int r   = rc >> 9;
                int ce  = (rc & (W-1)) + 3;
                int cst = ce - n + 1;
                float* a = &s_acc[lab*8];
                atomicAdd(a+0, (float)n);
                atomicAdd(a+1, 0.5f * (float)((ce + cst) * n));
                atomicAdd(a+2, (float)(r * n));
                atomicAdd(a+3, s0);
                atomicAdd(a+4, s1);
                atomicAdd(a+5, s2);
                atomicAdd(a+6, s3);
                atomicAdd(a+7, s4);
                int* bb = &s_bb[lab*4];
                atomicMin(bb+0, r);   atomicMax(bb+1, r);
                atomicMin(bb+2, cst); atomicMax(bb+3, ce);
            }
        } else {
            int   ls[4] = {l4.x, l4.y, l4.z, l4.w};
            float f0[4] = {a0.x, a0.y, a0.z, a0.w};
            float f1[4] = {a1.x, a1.y, a1.z, a1.w};
            float f2[4] = {a2.x, a2.y, a2.z, a2.w};
            float f3[4] = {a3.x, a3.y, a3.z, a3.w};
            float f4[4] = {a4.x, a4.y, a4.z, a4.w};
#pragma unroll
            for (int e = 0; e < 4; e++) {
                int lab = ls[e];
                if (lab >= 1 && lab <= K) {
                    int rce = rc + e;
                    int r = rce >> 9, c = rce & (W-1);
                    float* a = &s_acc[lab*8];
                    atomicAdd(a+0, 1.f);
                    atomicAdd(a+1, (float)c);
                    atomicAdd(a+2, (float)r);
                    atomicAdd(a+3, f0[e]);
                    atomicAdd(a+4, f1[e]);
                    atomicAdd(a+5, f2[e]);
                    atomicAdd(a+6, f3[e]);
                    atomicAdd(a+7, f4[e]);
                    int* bb = &s_bb[lab*4];
                    atomicMin(bb+0, r); atomicMax(bb+1, r);
                    atomicMin(bb+2, c); atomicMax(bb+3, c);
                }
            }
        }
    }
    __syncthreads();

    // flush to global (one label per thread)
    {
        int lab = tid + 1;
        if (lab <= K && s_acc[lab*8] > 0.f) {
            float* g = &g_stats[(b*(K+1) + lab)*8];
#pragma unroll
            for (int t = 0; t < 8; t++) atomicAdd(g + t, s_acc[lab*8 + t]);
            int* gb = &g_bbox[(b*K + lab - 1)*4];
            atomicMin(gb+0, s_bb[lab*4+0]); atomicMax(gb+1, s_bb[lab*4+1]);
            atomicMin(gb+2, s_bb[lab*4+2]); atomicMax(gb+3, s_bb[lab*4+3]);
        }
    }

    // Correct ordering: each thread fences its own global atomics, then the
    // block syncs, THEN tid0 bumps the counter.
    __threadfence();
    __syncthreads();
    if (tid == 0) {
        unsigned prev = atomicAdd(&g_cnt_stats, 1u);
        s_last = (prev == gridDim.x - 1);
        if (s_last) g_cnt_stats = 0u;
    }
    __syncthreads();
    if (!s_last) return;
    __threadfence();

    for (int idx2 = tid; idx2 < NB*K; idx2 += 256) {
        int bb2 = idx2 / K, k = idx2 % K;
        const float* st = &g_stats[(bb2*(K+1) + k + 1)*8];
        float cnt  = st[0];
        float safe = fmaxf(cnt, 1.f);
        float bx = st[1]/safe, by = st[2]/safe, rem = st[3]/safe;
        float ti = st[4]/safe, tj = st[5]/safe;
        float r  = st[6]/safe, s  = st[7]/safe;
        bool valid = (cnt > 0.f) && (rem < 0.5f);
        int* db = &g_dbox[idx2*4];
        if (!valid) { db[0]=1; db[1]=0; db[2]=1; db[3]=0; continue; }

        float half = (float)(W/2);
        float bxn = (half - bx)/half;
        float byn = (half - by)/half;
        float cR = cosf(r), sn = sinf(r);
        float p = 1.f + s;
        float h00 = p*cR,  h01 = -p*sn;
        float h02 = p*(cR*bxn - sn*byn) - bxn + ti;
        float h10 = p*sn,  h11 =  p*cR;
        float h12 = p*(sn*bxn + cR*byn) - byn + tj;
        float D   = h00*h11 - h01*h10;
        float i00 =  h11/D, i01 = -h01/D, i02 = (h01*h12 - h11*h02)/D;
        float i10 = -h10/D, i11 =  h00/D, i12 = (h10*h02 - h00*h12)/D;
        float* cf = &g_coef[idx2*6];
        cf[0]=i00; cf[1]=i01; cf[2]=i02; cf[3]=i10; cf[4]=i11; cf[5]=i12;

        const int* sb = &g_bbox[idx2*4];
        float ulo = 2.f*((float)sb[2]-0.5f)/(float)(W-1) - 1.f;
        float uhi = 2.f*((float)sb[3]+0.5f)/(float)(W-1) - 1.f;
        float vlo = 2.f*((float)sb[0]-0.5f)/(float)(H-1) - 1.f;
        float vhi = 2.f*((float)sb[1]+0.5f)/(float)(H-1) - 1.f;
        float xmin=1e30f, xmax=-1e30f, ymin=1e30f, ymax=-1e30f;
#pragma unroll
        for (int ci = 0; ci < 4; ci++) {
            float u = (ci & 1) ? uhi : ulo;
            float v = (ci & 2) ? vhi : vlo;
            float dx = h00*u + h01*v + h02;
            float dy = h10*u + h11*v + h12;
            xmin = fminf(xmin, dx); xmax = fmaxf(xmax, dx);
            ymin = fminf(ymin, dy); ymax = fmaxf(ymax, dy);
        }
        int c0 = max(0,   (int)floorf((xmin+1.f)*(float)(W-1)*0.5f) - 2);
        int c1 = min(W-1, (int)ceilf ((xmax+1.f)*(float)(W-1)*0.5f) + 2);
        int r0 = max(0,   (int)floorf((ymin+1.f)*(float)(H-1)*0.5f) - 2);
        int r1 = min(H-1, (int)ceilf ((ymax+1.f)*(float)(H-1)*0.5f) + 2);
        db[0]=r0; db[1]=r1; db[2]=c0; db[3]=c1;
    }
}

// ---------------------------------------------------------------------------
// One block per (b,k): scan dest bbox with 4 independent gathers in flight.
__global__ void scan_kernel(const int* __restrict__ labels) {
    int id = blockIdx.x;
    int b = id / K, k = id % K;
    const int* db = &g_dbox[id*4];
    int r0 = db[0], r1 = db[1], c0 = db[2], c1 = db[3];
    if (r0 > r1 || c0 > c1) return;
    const float* cf = &g_coef[id*6];
    float i00=cf[0], i01=cf[1], i02=cf[2], i10=cf[3], i11=cf[4], i12=cf[5];
    int bw  = c1 - c0 + 1;
    int tot = bw * (r1 - r0 + 1);
    const int* lb = labels + b*HW;
    float* pj = g_proj + b*HW;
    const float step = 2.0f/511.0f;
    int match = k + 1;

    for (int t0 = threadIdx.x; t0 < tot; t0 += 1024) {
        int px[4], py[4], src[4];
#pragma unroll
        for (int u = 0; u < 4; u++) {
            int t = t0 + u*256;
            src[u] = 0;
            if (t < tot) {
                px[u] = c0 + t % bw;
                py[u] = r0 + t / bw;
                float gx = -1.f + (float)px[u] * step;
                float gy = -1.f + (float)py[u] * step;
                int ix = __float2int_rn((i00*gx + i01*gy + i02 + 1.f) * 255.5f);
                int iy = __float2int_rn((i10*gx + i11*gy + i12 + 1.f) * 255.5f);
                bool ok = (ix >= 0) & (ix < W) & (iy >= 0) & (iy < H);
                src[u] = ok ? __ldg(&lb[iy*W + ix]) : 0;
            }
        }
#pragma unroll
        for (int u = 0; u < 4; u++)
            if (src[u] == match) atomicAdd(&pj[py[u]*W + px[u]], 1.f);
    }
}

// ---------------------------------------------------------------------------
// Mask write + cropped-loss reduction. 4 float4 groups per thread, all loads
// front-batched (MLP=8). Warp shfl reduce (double), global double atomics.
__global__ void loss_final_kernel(const float* __restrict__ gti,
                                  float* __restrict__ mask_out,
                                  float* __restrict__ out, int write_loss) {
    __shared__ double s_sq[8], s_ab[8];
    __shared__ bool s_last;
    int tid  = threadIdx.x;
    int lane = tid & 31;
    int wid  = tid >> 5;
    int base = blockIdx.x*1024 + tid;       // group index, +j*256

    float4 p[4], g[4];
#pragma unroll
    for (int j = 0; j < 4; j++) p[j] = ((const float4*)g_proj)[base + j*256];
#pragma unroll
    for (int j = 0; j < 4; j++) g[j] = ((const float4*)gti)[base + j*256];

    float lsq = 0.f, lab = 0.f;
#pragma unroll
    for (int j = 0; j < 4; j++) {
        int i = (base + j*256) * 4;
        mask_out[i+0] = (p[j].x != 0.f) ? 1.f : 0.f;
        mask_out[i+1] = (p[j].y != 0.f) ? 1.f : 0.f;
        mask_out[i+2] = (p[j].z != 0.f) ? 1.f : 0.f;
        mask_out[i+3] = (p[j].w != 0.f) ? 1.f : 0.f;
        int rc = i & (HW-1);
        int r = rc >> 9, c = rc & (W-1);
        if (r >= BORDER && r < H-BORDER) {
            float dx = p[j].x - g[j].x, dy = p[j].y - g[j].y;
            float dz = p[j].z - g[j].z, dw = p[j].w - g[j].w;
            if (c+0 >= BORDER && c+0 < W-BORDER) { lsq += dx*dx; lab += fabsf(dx); }
            if (c+1 >= BORDER && c+1 < W-BORDER) { lsq += dy*dy; lab += fabsf(dy); }
            if (c+2 >= BORDER && c+2 < W-BORDER) { lsq += dz*dz; lab += fabsf(dz); }
            if (c+3 >= BORDER && c+3 < W-BORDER) { lsq += dw*dw; lab += fabsf(dw); }
        }
    }
    double dsq = (double)lsq, dab = (double)lab;
#pragma unroll
    for (int off = 16; off > 0; off >>= 1) {
        dsq += __shfl_down_sync(0xFFFFFFFFu, dsq, off);
        dab += __shfl_down_sync(0xFFFFFFFFu, dab, off);
    }
    if (lane == 0) { s_sq[wid] = dsq; s_ab[wid] = dab; }
    __syncthreads();
    if (tid == 0) {
        double a = 0.0, bb = 0.0;
#pragma unroll
        for (int w = 0; w < 8; w++) { a += s_sq[w]; bb += s_ab[w]; }
        atomicAdd(&g_loss_sq, a);
        atomicAdd(&g_loss_ab, bb);
        // Same thread performed the loss atomics -> single-thread fence orders
        // them before the counter bump.
        __threadfence();
        unsigned prev = atomicAdd(&g_cnt_loss, 1u);
        s_last = (prev == gridDim.x - 1);
        if (s_last) g_cnt_loss = 0u;
    }
    __syncthreads();
    if (!s_last) return;
    if (tid == 0 && write_loss) {
        __threadfence();
        double N = (double)NB * (double)(H-2*BORDER) * (double)(W-2*BORDER);
        out[0] = (float)(g_loss_sq/N + g_loss_ab/N);
    }
}

// ---------------------------------------------------------------------------
// Inputs (metadata order): rgb, mod, gti, seg_inj, trs, rot, sca, labels
extern "C" void kernel_launch(void* const* d_in, const int* in_sizes, int n_in,
                              void* d_out, int out_size) {
    const float* gti    = (const float*)d_in[2];
    const float* inj    = (const float*)d_in[3];
    const float* trs    = (const float*)d_in[4];
    const float* rot    = (const float*)d_in[5];
    const float* sca    = (const float*)d_in[6];
    const int*   labels = (const int*)  d_in[7];
    float* out = (float*)d_out;

    int extra = out_size - NB*HW;          // expected 1 (loss scalar first)
    float* mask_out = out + (extra > 0 ? extra : 0);
    int write_loss = (extra > 0) ? 1 : 0;

    init_kernel      <<<16, 256>>>();
    stats_prep_kernel<<<SBLK, 256>>>(labels, inj, trs, rot, sca);
    scan_kernel      <<<NB*K, 256>>>(labels);
    loss_final_kernel<<<LBLK, 256>>>(gti, mask_out, out, write_loss);
}